// round 8
// baseline (speedup 1.0000x reference)
#include <cuda_runtime.h>
#include <cstdint>

// PaddedNeighModule: pair_first = repeat(arange(n_atoms), 64) -> contiguous
// 64-pair segments. Per atom: stable-sort by pair_second, emit jlist (float)
// and permuted coords.
//
// FOUR atoms per warp (8-lane groups). 8 elements/thread (ids 8*ll+reg);
// bitonic on keys (second<<6)|id, only 6 of 21 stages shuffle. Coord loads
// DEFERRED until after the sort (low register pressure). Shared buffers padded
// (200-float / 72-byte group strides) to kill systematic bank conflicts.

#define WARPS_PER_BLOCK 8
#define ATOMS_PER_WARP 4
#define ATOMS_PER_BLOCK (WARPS_PER_BLOCK * ATOMS_PER_WARP)   // 32
#define THREADS (WARPS_PER_BLOCK * 32)
#define GRP_F 200              // padded floats per atom group (192 + 8)
#define MAP_B 72               // padded map bytes per atom group (64 + 8)

#define CMPX(a, b, asc)                                   \
    {                                                     \
        unsigned _lo = min(a, b), _hi = max(a, b);        \
        (a) = (asc) ? _lo : _hi;                          \
        (b) = (asc) ? _hi : _lo;                          \
    }

// in-thread bitonic merge j=4,2,1 over v0..v7, single direction
#define LOCAL8(dir)                                                         \
    CMPX(v0, v4, dir); CMPX(v1, v5, dir); CMPX(v2, v6, dir); CMPX(v3, v7, dir); \
    CMPX(v0, v2, dir); CMPX(v1, v3, dir); CMPX(v4, v6, dir); CMPX(v5, v7, dir); \
    CMPX(v0, v1, dir); CMPX(v2, v3, dir); CMPX(v4, v5, dir); CMPX(v6, v7, dir);

// shuffle compare-exchange over all 8 regs, distance d (stays inside 8-lane group)
#define SHFL8(d, km)                                                          \
    {                                                                         \
        const bool _k = (km);                                                 \
        unsigned _p;                                                          \
        _p = __shfl_xor_sync(0xffffffffu, v0, (d)); v0 = _k ? min(v0, _p) : max(v0, _p); \
        _p = __shfl_xor_sync(0xffffffffu, v1, (d)); v1 = _k ? min(v1, _p) : max(v1, _p); \
        _p = __shfl_xor_sync(0xffffffffu, v2, (d)); v2 = _k ? min(v2, _p) : max(v2, _p); \
        _p = __shfl_xor_sync(0xffffffffu, v3, (d)); v3 = _k ? min(v3, _p) : max(v3, _p); \
        _p = __shfl_xor_sync(0xffffffffu, v4, (d)); v4 = _k ? min(v4, _p) : max(v4, _p); \
        _p = __shfl_xor_sync(0xffffffffu, v5, (d)); v5 = _k ? min(v5, _p) : max(v5, _p); \
        _p = __shfl_xor_sync(0xffffffffu, v6, (d)); v6 = _k ? min(v6, _p) : max(v6, _p); \
        _p = __shfl_xor_sync(0xffffffffu, v7, (d)); v7 = _k ? min(v7, _p) : max(v7, _p); \
    }

__global__ __launch_bounds__(THREADS, 8) void padded_neigh_kernel(
    const int*   __restrict__ pair_second,
    const float* __restrict__ pair_coord,
    float*       __restrict__ jlist_out,   // [n_atoms * 64]
    float*       __restrict__ rij_out,     // [n_atoms * 64 * 3]
    int n_atoms)
{
    __shared__ __align__(16) float sho[WARPS_PER_BLOCK][ATOMS_PER_WARP * GRP_F];
    __shared__ unsigned char       shs[WARPS_PER_BLOCK][ATOMS_PER_WARP * MAP_B];

    const int warp = threadIdx.x >> 5;
    const int lane = threadIdx.x & 31;
    const int ll   = lane & 7;       // lane within 8-lane atom group
    const int g    = lane >> 3;      // atom group 0..3

    const int atom0 = blockIdx.x * ATOMS_PER_BLOCK + warp * ATOMS_PER_WARP;
    const int atom  = atom0 + g;
    const bool valid = (atom < n_atoms);
    const int satom = valid ? atom : (n_atoms - 1);   // safe load address
    const int base  = satom * 64;

    // ---- keys: two LDG.128, elements 8*ll .. 8*ll+7 ----
    const int4 ka = ((const int4*)(pair_second + base))[2 * ll];
    const int4 kb = ((const int4*)(pair_second + base))[2 * ll + 1];
    unsigned v0 = ((unsigned)ka.x << 6) | (unsigned)(8 * ll + 0);
    unsigned v1 = ((unsigned)ka.y << 6) | (unsigned)(8 * ll + 1);
    unsigned v2 = ((unsigned)ka.z << 6) | (unsigned)(8 * ll + 2);
    unsigned v3 = ((unsigned)ka.w << 6) | (unsigned)(8 * ll + 3);
    unsigned v4 = ((unsigned)kb.x << 6) | (unsigned)(8 * ll + 4);
    unsigned v5 = ((unsigned)kb.y << 6) | (unsigned)(8 * ll + 5);
    unsigned v6 = ((unsigned)kb.z << 6) | (unsigned)(8 * ll + 6);
    unsigned v7 = ((unsigned)kb.w << 6) | (unsigned)(8 * ll + 7);

    // ---- bitonic sort, 64 elements per group, id = 8*ll + reg ----
    CMPX(v0, v1, true);  CMPX(v2, v3, false);          // k=2
    CMPX(v4, v5, true);  CMPX(v6, v7, false);
    CMPX(v0, v2, true);  CMPX(v1, v3, true);           // k=4
    CMPX(v4, v6, false); CMPX(v5, v7, false);
    CMPX(v0, v1, true);  CMPX(v2, v3, true);
    CMPX(v4, v5, false); CMPX(v6, v7, false);
    {
        const bool dir = ((ll & 1) == 0);              // k=8
        LOCAL8(dir);
    }
    {
        const bool dir = ((ll & 2) == 0);              // k=16
        SHFL8(1, (((ll & 1) == 0) == dir));
        LOCAL8(dir);
    }
    {
        const bool dir = ((ll & 4) == 0);              // k=32
        SHFL8(2, (((ll & 2) == 0) == dir));
        SHFL8(1, (((ll & 1) == 0) == dir));
        LOCAL8(dir);
    }
    {
        SHFL8(4, ((ll & 4) == 0));                     // k=64 (ascending)
        SHFL8(2, ((ll & 2) == 0));
        SHFL8(1, ((ll & 1) == 0));
        LOCAL8(true);
    }
    // thread holds ranks 8*ll .. 8*ll+7 (ascending keys)

    // ---- jlist: 8 consecutive ranks -> two STG.128 ----
    if (valid) {
        float4* j4 = (float4*)(jlist_out + base);
        j4[2 * ll]     = make_float4((float)(v0 >> 6), (float)(v1 >> 6),
                                     (float)(v2 >> 6), (float)(v3 >> 6));
        j4[2 * ll + 1] = make_float4((float)(v4 >> 6), (float)(v5 >> 6),
                                     (float)(v6 >> 6), (float)(v7 >> 6));
    }

    // ---- inverse permutation: sm[src] = rank ----
    unsigned char* sm = shs[warp] + g * MAP_B;
    sm[v0 & 63u] = (unsigned char)(8 * ll + 0);
    sm[v1 & 63u] = (unsigned char)(8 * ll + 1);
    sm[v2 & 63u] = (unsigned char)(8 * ll + 2);
    sm[v3 & 63u] = (unsigned char)(8 * ll + 3);
    sm[v4 & 63u] = (unsigned char)(8 * ll + 4);
    sm[v5 & 63u] = (unsigned char)(8 * ll + 5);
    sm[v6 & 63u] = (unsigned char)(8 * ll + 6);
    sm[v7 & 63u] = (unsigned char)(8 * ll + 7);
    __syncwarp();

    // ranks of this thread's own elements 8*ll..8*ll+7
    const uchar4 ra = ((const uchar4*)sm)[2 * ll];
    const uchar4 rb = ((const uchar4*)sm)[2 * ll + 1];

    // ---- DEFERRED coord loads, interleaved with scatter (<=2 float4 live) ----
    const float4* c4p = (const float4*)(pair_coord + (size_t)base * 3);
    float* o = sho[warp] + g * GRP_F;
    {
        float4 ca = c4p[6 * ll + 0];
        float4 cb = c4p[6 * ll + 1];
        int p;
        p = (int)ra.x * 3;  o[p] = ca.x;  o[p + 1] = ca.y;  o[p + 2] = ca.z;
        p = (int)ra.y * 3;  o[p] = ca.w;  o[p + 1] = cb.x;  o[p + 2] = cb.y;
        ca = c4p[6 * ll + 2];
        p = (int)ra.z * 3;  o[p] = cb.z;  o[p + 1] = cb.w;  o[p + 2] = ca.x;
        p = (int)ra.w * 3;  o[p] = ca.y;  o[p + 1] = ca.z;  o[p + 2] = ca.w;
        cb = c4p[6 * ll + 3];
        ca = c4p[6 * ll + 4];
        p = (int)rb.x * 3;  o[p] = cb.x;  o[p + 1] = cb.y;  o[p + 2] = cb.z;
        p = (int)rb.y * 3;  o[p] = cb.w;  o[p + 1] = ca.x;  o[p + 2] = ca.y;
        cb = c4p[6 * ll + 5];
        p = (int)rb.z * 3;  o[p] = ca.z;  o[p + 1] = ca.w;  o[p + 2] = cb.x;
        p = (int)rb.w * 3;  o[p] = cb.y;  o[p + 1] = cb.z;  o[p + 2] = cb.w;
    }
    __syncwarp();

    // ---- coalesced drain: 192 float4 per warp, padded source layout ----
    {
        const long total4 = (long)n_atoms * 48;
        const long wbase4 = (long)atom0 * 48;
        float4*       r4 = (float4*)rij_out + wbase4;
        const float4* s4 = (const float4*)sho[warp];
#pragma unroll
        for (int t = 0; t < 6; t++) {
            const int idx = lane + 32 * t;               // 0..191
            const int grp = idx / 48;
            const int within = idx - 48 * grp;
            if (wbase4 + idx < total4)
                r4[idx] = s4[grp * (GRP_F / 4) + within];
        }
    }
}

extern "C" void kernel_launch(void* const* d_in, const int* in_sizes, int n_in,
                              void* d_out, int out_size)
{
    // inputs: [0] pair_first (unused), [1] pair_second, [2] pair_coord,
    //         [3] atom_array (unused, gives n_atoms), [4] n_neigh_max (=64)
    const int*   pair_second = (const int*)d_in[1];
    const float* pair_coord  = (const float*)d_in[2];
    const int    n_atoms     = in_sizes[3];

    float* jlist = (float*)d_out;                    // n_atoms*64
    float* rij   = jlist + (size_t)n_atoms * 64;     // n_atoms*64*3

    const int blocks = (n_atoms + ATOMS_PER_BLOCK - 1) / ATOMS_PER_BLOCK;
    padded_neigh_kernel<<<blocks, THREADS>>>(pair_second, pair_coord, jlist, rij, n_atoms);
}